// round 4
// baseline (speedup 1.0000x reference)
#include <cuda_runtime.h>
#include <cuda_bf16.h>
#include <cstdint>

#define IN_DIM  128
#define HID_DIM 128
#define OUT_DIM 64
#define MAX_N   100000
#define MAX_E   1700000

// ---------------- device scratch ----------------
__device__ int   g_cnt[MAX_N];      // in-degree (without self loop)
__device__ float g_dinv[MAX_N];
__device__ float g_s[MAX_N];
__device__ int   g_off[MAX_N];
__device__ int   g_cursor[MAX_N];
__device__ int   g_bsum[512];
__device__ int   g_bscan[512];
__device__ int   g_bin[MAX_E];
__device__ __nv_bfloat16 g_h0bf[(size_t)MAX_N * HID_DIM];
__device__ float g_y[HID_DIM];
__device__ int   g_is32;

__device__ __forceinline__ int load_idx(const void* ei, size_t i) {
    if (g_is32) return ((const int*)ei)[i];
    return (int)((const long long*)ei)[i];
}

// ---------------- zero counts + index dtype detection (fused) ----------------
__global__ void init_kernel(const void* ei, int n) {
    int i = blockIdx.x * blockDim.x + threadIdx.x;
    if (i < n) g_cnt[i] = 0;
    if (i == 0) {
        const long long* p = (const long long*)ei;
        int bad = 0;
        for (int k = 0; k < 8; k++) {
            long long v = p[k];
            if (v < 0 || v >= (long long)n) bad = 1;
        }
        g_is32 = bad;
    }
}

__global__ void count_deg_kernel(const void* ei, int E) {
    int e = blockIdx.x * blockDim.x + threadIdx.x;
    if (e >= E) return;
    int c = load_idx(ei, (size_t)E + e);
    atomicAdd(&g_cnt[c], 1);
}

// ---------------- scan1 + dinv (fused) ----------------
__global__ void scan1_kernel(int n) {
    __shared__ int sh[256];
    int t = threadIdx.x;
    int i = blockIdx.x * 256 + t;
    int v = (i < n) ? g_cnt[i] : 0;
    sh[t] = v;
    __syncthreads();
    #pragma unroll
    for (int ofs = 1; ofs < 256; ofs <<= 1) {
        int a = (t >= ofs) ? sh[t - ofs] : 0;
        __syncthreads();
        sh[t] += a;
        __syncthreads();
    }
    if (i < n) {
        g_off[i] = sh[t] - v;
        float d = rsqrtf((float)(v + 1));
        g_dinv[i] = d;
        g_s[i] = d;
    }
    if (t == 255) g_bsum[blockIdx.x] = sh[255];
}

// ---------------- scan2 + zero_y (fused) ----------------
__global__ void scan2_kernel(int nb) {
    __shared__ int sh[512];
    int t = threadIdx.x;
    if (t < 128) g_y[t] = 0.f;
    int v = (t < nb) ? g_bsum[t] : 0;
    sh[t] = v;
    __syncthreads();
    #pragma unroll
    for (int ofs = 1; ofs < 512; ofs <<= 1) {
        int a = (t >= ofs) ? sh[t - ofs] : 0;
        __syncthreads();
        sh[t] += a;
        __syncthreads();
    }
    g_bscan[t] = sh[t] - v;
}

__global__ void scan3_kernel(int n) {
    int i = blockIdx.x * blockDim.x + threadIdx.x;
    if (i >= n) return;
    int o = g_off[i] + g_bscan[i >> 8];
    g_off[i] = o;
    g_cursor[i] = o;
}

// ---------------- bin fill (+ s accumulation) ----------------
__global__ void binfill_kernel(const void* ei, int E) {
    int e = blockIdx.x * blockDim.x + threadIdx.x;
    if (e >= E) return;
    int r = load_idx(ei, e);
    int c = load_idx(ei, (size_t)E + e);
    atomicAdd(&g_s[r], g_dinv[c]);
    int pos = atomicAdd(&g_cursor[c], 1);
    g_bin[pos] = r;
}

// ---------------- GEMM1: h0 = bf16(x @ W1) via mma.sync bf16 ----------------
#define AS_STRIDE 136
__global__ __launch_bounds__(256) void gemm1_kernel(
    const float* __restrict__ x, const float* __restrict__ W, int n)
{
    __shared__ __nv_bfloat16 As[128][AS_STRIDE];
    __shared__ __nv_bfloat16 Ws[128][AS_STRIDE];   // transposed: [n][k]
    int t = threadIdx.x;
    int row0 = blockIdx.x * 128;

    const float4* xg = (const float4*)x;
    #pragma unroll
    for (int i = 0; i < 16; i++) {
        int idx4 = t + i * 256;
        int r = idx4 >> 5, c4 = idx4 & 31;
        float4 v = make_float4(0.f, 0.f, 0.f, 0.f);
        if (row0 + r < n) v = xg[(size_t)(row0 + r) * 32 + c4];
        *(__nv_bfloat162*)&As[r][c4 * 4]     = __floats2bfloat162_rn(v.x, v.y);
        *(__nv_bfloat162*)&As[r][c4 * 4 + 2] = __floats2bfloat162_rn(v.z, v.w);
    }
    const float4* wg = (const float4*)W;
    #pragma unroll
    for (int i = 0; i < 16; i++) {
        int idx4 = t + i * 256;
        int k = idx4 >> 5, n4 = idx4 & 31;
        float4 v = wg[idx4];
        Ws[n4 * 4 + 0][k] = __float2bfloat16(v.x);
        Ws[n4 * 4 + 1][k] = __float2bfloat16(v.y);
        Ws[n4 * 4 + 2][k] = __float2bfloat16(v.z);
        Ws[n4 * 4 + 3][k] = __float2bfloat16(v.w);
    }
    __syncthreads();

    int lane = t & 31, wid = t >> 5;
    int moff = (wid & 3) * 32;
    int noff = (wid >> 2) * 64;
    int g = lane >> 2, tq = lane & 3;

    float acc[2][8][4];
    #pragma unroll
    for (int mt = 0; mt < 2; mt++)
        #pragma unroll
        for (int nt = 0; nt < 8; nt++)
            #pragma unroll
            for (int j = 0; j < 4; j++) acc[mt][nt][j] = 0.f;

    #pragma unroll
    for (int kt = 0; kt < 8; kt++) {
        int k0 = kt * 16;
        uint32_t a[2][4];
        #pragma unroll
        for (int mt = 0; mt < 2; mt++) {
            int r = moff + mt * 16 + g;
            a[mt][0] = *(const uint32_t*)&As[r][k0 + 2 * tq];
            a[mt][1] = *(const uint32_t*)&As[r + 8][k0 + 2 * tq];
            a[mt][2] = *(const uint32_t*)&As[r][k0 + 2 * tq + 8];
            a[mt][3] = *(const uint32_t*)&As[r + 8][k0 + 2 * tq + 8];
        }
        #pragma unroll
        for (int nt = 0; nt < 8; nt++) {
            int c = noff + nt * 8 + g;
            uint32_t b0 = *(const uint32_t*)&Ws[c][k0 + 2 * tq];
            uint32_t b1 = *(const uint32_t*)&Ws[c][k0 + 2 * tq + 8];
            #pragma unroll
            for (int mt = 0; mt < 2; mt++) {
                asm volatile(
                    "mma.sync.aligned.m16n8k16.row.col.f32.bf16.bf16.f32 "
                    "{%0,%1,%2,%3}, {%4,%5,%6,%7}, {%8,%9}, {%0,%1,%2,%3};"
                    : "+f"(acc[mt][nt][0]), "+f"(acc[mt][nt][1]),
                      "+f"(acc[mt][nt][2]), "+f"(acc[mt][nt][3])
                    : "r"(a[mt][0]), "r"(a[mt][1]), "r"(a[mt][2]), "r"(a[mt][3]),
                      "r"(b0), "r"(b1));
            }
        }
    }

    #pragma unroll
    for (int mt = 0; mt < 2; mt++) {
        int r = row0 + moff + mt * 16 + g;
        #pragma unroll
        for (int nt = 0; nt < 8; nt++) {
            int c = noff + nt * 8 + 2 * tq;
            if (r < n)
                *(__nv_bfloat162*)&g_h0bf[(size_t)r * 128 + c] =
                    __floats2bfloat162_rn(acc[mt][nt][0], acc[mt][nt][1]);
            if (r + 8 < n)
                *(__nv_bfloat162*)&g_h0bf[(size_t)(r + 8) * 128 + c] =
                    __floats2bfloat162_rn(acc[mt][nt][2], acc[mt][nt][3]);
        }
    }
}

// ---------------- fused conv1 + relu + weighted reduce (bf16 gather) --------
__device__ __forceinline__ void fma4bf(float4& a, float s, uint2 u) {
    float2 f0 = __bfloat1622float2(*(__nv_bfloat162*)&u.x);
    float2 f1 = __bfloat1622float2(*(__nv_bfloat162*)&u.y);
    a.x = fmaf(s, f0.x, a.x);
    a.y = fmaf(s, f0.y, a.y);
    a.z = fmaf(s, f1.x, a.z);
    a.w = fmaf(s, f1.y, a.w);
}

__global__ __launch_bounds__(256) void fused_conv_kernel(
    const float* __restrict__ b1, int n)
{
    __shared__ float ysh[8 * 128];
    int t = threadIdx.x, lane = t & 31, w = t >> 5;
    float4 bb = ((const float4*)b1)[lane];
    float4 yacc = make_float4(0.f, 0.f, 0.f, 0.f);
    const uint2* h = (const uint2*)g_h0bf;   // 32 x 8B per row

    int gw = blockIdx.x * 8 + w;
    int nw = gridDim.x * 8;
    for (int v = gw; v < n; v += nw) {
        float dv = g_dinv[v];
        int off = g_off[v];
        int cnt = g_cnt[v];

        float4 a0 = make_float4(0.f, 0.f, 0.f, 0.f);
        float4 a1 = a0, a2 = a0, a3 = a0;
        fma4bf(a0, dv * dv, h[(size_t)v * 32 + lane]);   // self loop

        int k = 0;
        for (; k + 4 <= cnt; k += 4) {
            // 4 independent index loads -> 4 independent dinv loads ->
            // 4 independent gathers -> 4 separate accumulators (MLP=4)
            int s0 = g_bin[off + k];
            int s1 = g_bin[off + k + 1];
            int s2 = g_bin[off + k + 2];
            int s3 = g_bin[off + k + 3];
            float n0 = g_dinv[s0], n1 = g_dinv[s1];
            float n2 = g_dinv[s2], n3 = g_dinv[s3];
            uint2 u0 = h[(size_t)s0 * 32 + lane];
            uint2 u1 = h[(size_t)s1 * 32 + lane];
            uint2 u2 = h[(size_t)s2 * 32 + lane];
            uint2 u3 = h[(size_t)s3 * 32 + lane];
            fma4bf(a0, dv * n0, u0);
            fma4bf(a1, dv * n1, u1);
            fma4bf(a2, dv * n2, u2);
            fma4bf(a3, dv * n3, u3);
        }
        for (; k < cnt; k++) {
            int src = g_bin[off + k];
            float nr = g_dinv[src];
            fma4bf(a1, dv * nr, h[(size_t)src * 32 + lane]);
        }

        float4 a = make_float4(a0.x + a1.x + a2.x + a3.x,
                               a0.y + a1.y + a2.y + a3.y,
                               a0.z + a1.z + a2.z + a3.z,
                               a0.w + a1.w + a2.w + a3.w);

        float cv = dv * g_s[v];
        yacc.x = fmaf(cv, fmaxf(a.x + bb.x, 0.f), yacc.x);
        yacc.y = fmaf(cv, fmaxf(a.y + bb.y, 0.f), yacc.y);
        yacc.z = fmaf(cv, fmaxf(a.z + bb.z, 0.f), yacc.z);
        yacc.w = fmaf(cv, fmaxf(a.w + bb.w, 0.f), yacc.w);
    }

    *((float4*)&ysh[w * 128 + lane * 4]) = yacc;
    __syncthreads();
    if (t < 128) {
        float s = 0.f;
        #pragma unroll
        for (int i = 0; i < 8; i++) s += ysh[i * 128 + t];
        atomicAdd(&g_y[t], s);
    }
}

// ---------------- final: out = (y @ W2)/N + b2 ----------------
__global__ void final_kernel(const float* __restrict__ W2,
                             const float* __restrict__ b2,
                             float* __restrict__ out, int n)
{
    int f = threadIdx.x;   // 64
    float sum = 0.f;
    #pragma unroll 8
    for (int k = 0; k < 128; k++)
        sum = fmaf(g_y[k], W2[k * 64 + f], sum);
    out[f] = sum / (float)n + b2[f];
}

// ---------------- launch ----------------
extern "C" void kernel_launch(void* const* d_in, const int* in_sizes, int n_in,
                              void* d_out, int out_size)
{
    const float* x  = (const float*)d_in[0];
    const void*  ei = d_in[1];
    const float* W1 = (const float*)d_in[2];
    const float* b1 = (const float*)d_in[3];
    const float* W2 = (const float*)d_in[4];
    const float* b2 = (const float*)d_in[5];
    float* out = (float*)d_out;

    int n = in_sizes[0] / IN_DIM;     // 100000
    int E = in_sizes[1] / 2;          // 1600000
    int nb = (n + 255) / 256;         // scan blocks (<=512)

    init_kernel<<<(n + 255) / 256, 256>>>(ei, n);
    count_deg_kernel<<<(E + 255) / 256, 256>>>(ei, E);

    scan1_kernel<<<nb, 256>>>(n);
    scan2_kernel<<<1, 512>>>(nb);
    scan3_kernel<<<(n + 255) / 256, 256>>>(n);

    binfill_kernel<<<(E + 255) / 256, 256>>>(ei, E);

    gemm1_kernel<<<(n + 127) / 128, 256>>>(x, W1, n);

    fused_conv_kernel<<<1776, 256>>>(b1, n);
    final_kernel<<<1, 64>>>(W2, b2, out, n);
}

// round 5
// speedup vs baseline: 1.2196x; 1.2196x over previous
#include <cuda_runtime.h>
#include <cuda_bf16.h>
#include <cstdint>

#define IN_DIM  128
#define HID_DIM 128
#define OUT_DIM 64
#define MAX_N   100000
#define MAX_E   1700000

// ---------------- device scratch ----------------
__device__ int   g_cnt[MAX_N];      // in-degree (without self loop)
__device__ float g_dinv[MAX_N];
__device__ float g_s[MAX_N];
__device__ int   g_off[MAX_N];
__device__ int   g_cursor[MAX_N];
__device__ int   g_bsum[512];
__device__ int   g_bscan[512];
__device__ int   g_bin[MAX_E];
__device__ __nv_bfloat16 g_h0bf[(size_t)MAX_N * HID_DIM];  // dinv[v]*(x@W1)[v]
__device__ float g_y[HID_DIM];
__device__ int   g_is32;

__device__ __forceinline__ int load_idx(const void* ei, size_t i) {
    if (g_is32) return ((const int*)ei)[i];
    return (int)((const long long*)ei)[i];
}

// ---------------- zero counts + index dtype detection (fused) ----------------
__global__ void init_kernel(const void* ei, int n) {
    int i = blockIdx.x * blockDim.x + threadIdx.x;
    if (i < n) g_cnt[i] = 0;
    if (i == 0) {
        const long long* p = (const long long*)ei;
        int bad = 0;
        for (int k = 0; k < 8; k++) {
            long long v = p[k];
            if (v < 0 || v >= (long long)n) bad = 1;
        }
        g_is32 = bad;
    }
}

__global__ void count_deg_kernel(const void* ei, int E) {
    int e = blockIdx.x * blockDim.x + threadIdx.x;
    if (e >= E) return;
    int c = load_idx(ei, (size_t)E + e);
    atomicAdd(&g_cnt[c], 1);
}

// ---------------- scan1 + dinv (fused) ----------------
__global__ void scan1_kernel(int n) {
    __shared__ int sh[256];
    int t = threadIdx.x;
    int i = blockIdx.x * 256 + t;
    int v = (i < n) ? g_cnt[i] : 0;
    sh[t] = v;
    __syncthreads();
    #pragma unroll
    for (int ofs = 1; ofs < 256; ofs <<= 1) {
        int a = (t >= ofs) ? sh[t - ofs] : 0;
        __syncthreads();
        sh[t] += a;
        __syncthreads();
    }
    if (i < n) {
        g_off[i] = sh[t] - v;
        float d = rsqrtf((float)(v + 1));
        g_dinv[i] = d;
        g_s[i] = d;
    }
    if (t == 255) g_bsum[blockIdx.x] = sh[255];
}

// ---------------- scan2 + zero_y (fused) ----------------
__global__ void scan2_kernel(int nb) {
    __shared__ int sh[512];
    int t = threadIdx.x;
    if (t < 128) g_y[t] = 0.f;
    int v = (t < nb) ? g_bsum[t] : 0;
    sh[t] = v;
    __syncthreads();
    #pragma unroll
    for (int ofs = 1; ofs < 512; ofs <<= 1) {
        int a = (t >= ofs) ? sh[t - ofs] : 0;
        __syncthreads();
        sh[t] += a;
        __syncthreads();
    }
    g_bscan[t] = sh[t] - v;
}

__global__ void scan3_kernel(int n) {
    int i = blockIdx.x * blockDim.x + threadIdx.x;
    if (i >= n) return;
    int o = g_off[i] + g_bscan[i >> 8];
    g_off[i] = o;
    g_cursor[i] = o;
}

// ---------------- bin fill (+ s accumulation) ----------------
__global__ void binfill_kernel(const void* ei, int E) {
    int e = blockIdx.x * blockDim.x + threadIdx.x;
    if (e >= E) return;
    int r = load_idx(ei, e);
    int c = load_idx(ei, (size_t)E + e);
    atomicAdd(&g_s[r], g_dinv[c]);
    int pos = atomicAdd(&g_cursor[c], 1);
    g_bin[pos] = r;
}

// ---- GEMM1: h0' = bf16(dinv[row] * (x @ W1)) via mma.sync bf16 ----
#define AS_STRIDE 136
__global__ __launch_bounds__(256) void gemm1_kernel(
    const float* __restrict__ x, const float* __restrict__ W, int n)
{
    __shared__ __nv_bfloat16 As[128][AS_STRIDE];
    __shared__ __nv_bfloat16 Ws[128][AS_STRIDE];   // transposed: [n][k]
    int t = threadIdx.x;
    int row0 = blockIdx.x * 128;

    const float4* xg = (const float4*)x;
    #pragma unroll
    for (int i = 0; i < 16; i++) {
        int idx4 = t + i * 256;
        int r = idx4 >> 5, c4 = idx4 & 31;
        float4 v = make_float4(0.f, 0.f, 0.f, 0.f);
        if (row0 + r < n) v = xg[(size_t)(row0 + r) * 32 + c4];
        *(__nv_bfloat162*)&As[r][c4 * 4]     = __floats2bfloat162_rn(v.x, v.y);
        *(__nv_bfloat162*)&As[r][c4 * 4 + 2] = __floats2bfloat162_rn(v.z, v.w);
    }
    const float4* wg = (const float4*)W;
    #pragma unroll
    for (int i = 0; i < 16; i++) {
        int idx4 = t + i * 256;
        int k = idx4 >> 5, n4 = idx4 & 31;
        float4 v = wg[idx4];
        Ws[n4 * 4 + 0][k] = __float2bfloat16(v.x);
        Ws[n4 * 4 + 1][k] = __float2bfloat16(v.y);
        Ws[n4 * 4 + 2][k] = __float2bfloat16(v.z);
        Ws[n4 * 4 + 3][k] = __float2bfloat16(v.w);
    }
    __syncthreads();

    int lane = t & 31, wid = t >> 5;
    int moff = (wid & 3) * 32;
    int noff = (wid >> 2) * 64;
    int g = lane >> 2, tq = lane & 3;

    float acc[2][8][4];
    #pragma unroll
    for (int mt = 0; mt < 2; mt++)
        #pragma unroll
        for (int nt = 0; nt < 8; nt++)
            #pragma unroll
            for (int j = 0; j < 4; j++) acc[mt][nt][j] = 0.f;

    #pragma unroll
    for (int kt = 0; kt < 8; kt++) {
        int k0 = kt * 16;
        uint32_t a[2][4];
        #pragma unroll
        for (int mt = 0; mt < 2; mt++) {
            int r = moff + mt * 16 + g;
            a[mt][0] = *(const uint32_t*)&As[r][k0 + 2 * tq];
            a[mt][1] = *(const uint32_t*)&As[r + 8][k0 + 2 * tq];
            a[mt][2] = *(const uint32_t*)&As[r][k0 + 2 * tq + 8];
            a[mt][3] = *(const uint32_t*)&As[r + 8][k0 + 2 * tq + 8];
        }
        #pragma unroll
        for (int nt = 0; nt < 8; nt++) {
            int c = noff + nt * 8 + g;
            uint32_t b0 = *(const uint32_t*)&Ws[c][k0 + 2 * tq];
            uint32_t b1 = *(const uint32_t*)&Ws[c][k0 + 2 * tq + 8];
            #pragma unroll
            for (int mt = 0; mt < 2; mt++) {
                asm volatile(
                    "mma.sync.aligned.m16n8k16.row.col.f32.bf16.bf16.f32 "
                    "{%0,%1,%2,%3}, {%4,%5,%6,%7}, {%8,%9}, {%0,%1,%2,%3};"
                    : "+f"(acc[mt][nt][0]), "+f"(acc[mt][nt][1]),
                      "+f"(acc[mt][nt][2]), "+f"(acc[mt][nt][3])
                    : "r"(a[mt][0]), "r"(a[mt][1]), "r"(a[mt][2]), "r"(a[mt][3]),
                      "r"(b0), "r"(b1));
            }
        }
    }

    #pragma unroll
    for (int mt = 0; mt < 2; mt++) {
        int r = row0 + moff + mt * 16 + g;
        float d0 = (r < n) ? g_dinv[r] : 0.f;
        float d1 = (r + 8 < n) ? g_dinv[r + 8] : 0.f;
        #pragma unroll
        for (int nt = 0; nt < 8; nt++) {
            int c = noff + nt * 8 + 2 * tq;
            if (r < n)
                *(__nv_bfloat162*)&g_h0bf[(size_t)r * 128 + c] =
                    __floats2bfloat162_rn(d0 * acc[mt][nt][0], d0 * acc[mt][nt][1]);
            if (r + 8 < n)
                *(__nv_bfloat162*)&g_h0bf[(size_t)(r + 8) * 128 + c] =
                    __floats2bfloat162_rn(d1 * acc[mt][nt][2], d1 * acc[mt][nt][3]);
        }
    }
}

// ---------------- fused conv1 + relu + weighted reduce (bf16 gather) --------
__device__ __forceinline__ void add4bf(float4& a, uint2 u) {
    float2 f0 = __bfloat1622float2(*(__nv_bfloat162*)&u.x);
    float2 f1 = __bfloat1622float2(*(__nv_bfloat162*)&u.y);
    a.x += f0.x; a.y += f0.y; a.z += f1.x; a.w += f1.y;
}

__global__ __launch_bounds__(256) void fused_conv_kernel(
    const float* __restrict__ b1, int n)
{
    __shared__ float ysh[8 * 128];
    int t = threadIdx.x, lane = t & 31, w = t >> 5;
    float4 bb = ((const float4*)b1)[lane];
    float4 yacc = make_float4(0.f, 0.f, 0.f, 0.f);
    const uint2* h = (const uint2*)g_h0bf;   // 32 x 8B per row

    int gw = blockIdx.x * 8 + w;
    int nw = gridDim.x * 8;
    for (int v = gw; v < n; v += nw) {
        float dv = g_dinv[v];
        int off = g_off[v];
        int cnt = g_cnt[v];

        float4 a0 = make_float4(0.f, 0.f, 0.f, 0.f);
        float4 a1 = a0;
        add4bf(a0, h[(size_t)v * 32 + lane]);   // self loop (h already *dinv)

        int k = 0;
        for (; k + 2 <= cnt; k += 2) {
            int s0 = g_bin[off + k];
            int s1 = g_bin[off + k + 1];
            uint2 u0 = h[(size_t)s0 * 32 + lane];
            uint2 u1 = h[(size_t)s1 * 32 + lane];
            add4bf(a0, u0);
            add4bf(a1, u1);
        }
        if (k < cnt)
            add4bf(a1, h[(size_t)g_bin[off + k] * 32 + lane]);

        float cv = dv * g_s[v];
        yacc.x = fmaf(cv, fmaxf(fmaf(dv, a0.x + a1.x, bb.x), 0.f), yacc.x);
        yacc.y = fmaf(cv, fmaxf(fmaf(dv, a0.y + a1.y, bb.y), 0.f), yacc.y);
        yacc.z = fmaf(cv, fmaxf(fmaf(dv, a0.z + a1.z, bb.z), 0.f), yacc.z);
        yacc.w = fmaf(cv, fmaxf(fmaf(dv, a0.w + a1.w, bb.w), 0.f), yacc.w);
    }

    *((float4*)&ysh[w * 128 + lane * 4]) = yacc;
    __syncthreads();
    if (t < 128) {
        float s = 0.f;
        #pragma unroll
        for (int i = 0; i < 8; i++) s += ysh[i * 128 + t];
        atomicAdd(&g_y[t], s);
    }
}

// ---------------- final: out = (y @ W2)/N + b2 ----------------
__global__ void final_kernel(const float* __restrict__ W2,
                             const float* __restrict__ b2,
                             float* __restrict__ out, int n)
{
    int f = threadIdx.x;   // 64
    float sum = 0.f;
    #pragma unroll 8
    for (int k = 0; k < 128; k++)
        sum = fmaf(g_y[k], W2[k * 64 + f], sum);
    out[f] = sum / (float)n + b2[f];
}

// ---------------- launch ----------------
extern "C" void kernel_launch(void* const* d_in, const int* in_sizes, int n_in,
                              void* d_out, int out_size)
{
    const float* x  = (const float*)d_in[0];
    const void*  ei = d_in[1];
    const float* W1 = (const float*)d_in[2];
    const float* b1 = (const float*)d_in[3];
    const float* W2 = (const float*)d_in[4];
    const float* b2 = (const float*)d_in[5];
    float* out = (float*)d_out;

    int n = in_sizes[0] / IN_DIM;     // 100000
    int E = in_sizes[1] / 2;          // 1600000
    int nb = (n + 255) / 256;         // scan blocks (<=512)

    init_kernel<<<(n + 255) / 256, 256>>>(ei, n);
    count_deg_kernel<<<(E + 255) / 256, 256>>>(ei, E);

    scan1_kernel<<<nb, 256>>>(n);
    scan2_kernel<<<1, 512>>>(nb);
    scan3_kernel<<<(n + 255) / 256, 256>>>(n);

    binfill_kernel<<<(E + 255) / 256, 256>>>(ei, E);

    gemm1_kernel<<<(n + 127) / 128, 256>>>(x, W1, n);

    fused_conv_kernel<<<1776, 256>>>(b1, n);
    final_kernel<<<1, 64>>>(W2, b2, out, n);
}